// round 10
// baseline (speedup 1.0000x reference)
#include <cuda_runtime.h>
#include <math.h>

#define NN    8192
#define EE    262144
#define CC    64
#define ELLW  128   // Poisson(32) tail beyond 128 ~ 1e-40

// ---- scratch (__device__ globals; zeroed at module load) ----
__device__ int    g_cnt[NN];           // raw scatter counts (self-reset by dedup)
__device__ int    g_cnt2[NN];          // deduped counts
__device__ float  g_deg[NN];
__device__ float  g_sinv[NN];          // rsqrt(deg)
__device__ int2   g_ellcj[NN * ELLW];  // raw: (col, edge id)
__device__ float2 g_ell[NN * ELLW];    // winners: (col_as_float, gated weight) — immutable after dedup
__device__ float  g_Xs[NN * CC];       // sinv[r] * x[r]
__device__ float  g_T1[NN * CC];
__device__ float  g_T1s[NN * CC];      // sinv[r] * T1[r]
__device__ float  g_T2[NN * CC];
__device__ float  g_gate;
__device__ int    g_is32;

__device__ __forceinline__ void load_rc(const void* ei, int j, int& r, int& c) {
    if (g_is32) {
        const int* e = (const int*)ei;
        r = e[j]; c = e[EE + j];
    } else {
        const long long* e = (const long long*)ei;
        r = (int)e[j]; c = (int)e[EE + j];
    }
}

// 0) dtype detect + gate (one warp)
__global__ void k_setup(const void* ei, const float* __restrict__ aw) {
    const long long* e64 = (const long long*)ei;
    int lane = threadIdx.x;
    long long v0 = e64[lane];
    long long v1 = e64[32 + lane];
    int bad = (v0 < 0 || v0 >= NN || v1 < 0 || v1 >= NN);
    unsigned any = __any_sync(0xffffffffu, bad);
    if (lane == 0) {
        g_is32 = any ? 1 : 0;
        g_gate = 1.0f / (1.0f + expf(-aw[0]));
    }
}

// 1) scatter edges into per-row lists (order nondeterministic; j recorded)
__global__ void k_scatter(const void* __restrict__ ei) {
    int j = blockIdx.x * blockDim.x + threadIdx.x;
    if (j >= EE) return;
    int r, c; load_rc(ei, j, r, c);
    int pos = atomicAdd(&g_cnt[r], 1);
    if (pos < ELLW) g_ellcj[r * ELLW + pos] = make_int2(c, j);
}

// 2) per-row dedupe via 256-slot per-warp shared hash.
//    entry = (col+1)<<18 | j  -> atomicMax = last-write-wins on edge id.
//    Also writes Xs[r] = sinv[r]*x[r]. Self-resets g_cnt[r].
__global__ void k_dedup(const float* __restrict__ ew,
                        const float* __restrict__ x) {
    __shared__ unsigned tab[8][256];
    int wid  = threadIdx.x >> 5;
    int lane = threadIdx.x & 31;
    #pragma unroll
    for (int i = 0; i < 8; i++) tab[wid][lane + 32 * i] = 0u;
    __syncwarp();

    int r = blockIdx.x * 8 + wid;
    int nnz = min(g_cnt[r], ELLW);

    for (int k = lane; k < nnz; k += 32) {
        int2 cj = g_ellcj[r * ELLW + k];
        unsigned c = (unsigned)cj.x;
        unsigned entry = ((c + 1u) << 18) | (unsigned)cj.y;
        unsigned h = (c * 2654435761u) >> 24;
        for (;;) {
            unsigned cur = tab[wid][h];
            if (cur == 0u) {
                unsigned old = atomicCAS(&tab[wid][h], 0u, entry);
                if (old == 0u) break;
                cur = old;
            }
            if ((cur >> 18) == c + 1u) { atomicMax(&tab[wid][h], entry); break; }
            h = (h + 1u) & 255u;
        }
    }
    __syncwarp();

    float gate = g_gate;
    float degsum = 0.0f;
    int outpos = 0;
    #pragma unroll
    for (int it = 0; it < 8; it++) {
        unsigned e = tab[wid][lane + 32 * it];
        bool alive = (e != 0u);
        int c = 0; float wv = 0.0f;
        if (alive) {
            c = (int)(e >> 18) - 1;
            int j = (int)(e & 0x3FFFFu);
            wv = __ldg(&ew[j]) * gate;
            degsum += wv;
        }
        unsigned bal = __ballot_sync(0xffffffffu, alive);
        int pos = outpos + __popc(bal & ((1u << lane) - 1u));
        if (alive) g_ell[r * ELLW + pos] = make_float2(__int_as_float(c), wv);
        outpos += __popc(bal);
    }
    #pragma unroll
    for (int off = 16; off > 0; off >>= 1)
        degsum += __shfl_xor_sync(0xffffffffu, degsum, off);
    degsum = __shfl_sync(0xffffffffu, degsum, 0);

    float d  = 1.0f + degsum;
    float si = rsqrtf(d);
    if (lane == 0) {
        g_cnt2[r] = outpos;
        g_deg[r]  = d;
        g_sinv[r] = si;
        g_cnt[r]  = 0;              // reset for next replay
    }
    // Xs[r] = sinv[r] * x[r]   (64 floats, float2 per lane)
    float2 xv = __ldg(&((const float2*)x)[r * 32 + lane]);
    xv.x *= si; xv.y *= si;
    ((float2*)g_Xs)[r * 32 + lane] = xv;
}

// chunked gather core over [beg, end): 8-deep forced MLP
__device__ __forceinline__ float2 gather8r(const float2* __restrict__ ell,
                                           const float2* __restrict__ z,
                                           int beg, int end, int lane) {
    float2 acc = make_float2(0.0f, 0.0f);
    for (int kb = beg; kb < end; kb += 8) {
        float2 e[8];
        #pragma unroll
        for (int u = 0; u < 8; u++) {
            e[u] = (kb + u < end) ? __ldg(&ell[kb + u])
                                  : make_float2(__int_as_float(0), 0.0f);
        }
        float2 zc[8];
        #pragma unroll
        for (int u = 0; u < 8; u++) {
            int c = __float_as_int(e[u].x);
            zc[u] = __ldg(&z[c * 32 + lane]);
        }
        #pragma unroll
        for (int u = 0; u < 8; u++) {
            acc.x = fmaf(e[u].y, zc[u].x, acc.x);
            acc.y = fmaf(e[u].y, zc[u].y, acc.y);
        }
    }
    return acc;
}

// 3) T1 = diag*x[r] - sr * sum w*Xs[c] ; also T1s = sr*T1
//    64 threads per row: warp-half 0/1 each gathers half the edges.
__global__ void k_spmm1(const float* __restrict__ x) {
    __shared__ float2 part[4][32];
    int gtid = blockIdx.x * blockDim.x + threadIdx.x;
    int r    = gtid >> 6;
    int half = (threadIdx.x >> 5) & 1;
    int lane = threadIdx.x & 31;
    int rl   = threadIdx.x >> 6;          // 0..3

    int nnz = g_cnt2[r];
    int n0  = (nnz + 1) >> 1;
    int beg = half ? n0 : 0;
    int end = half ? nnz : n0;

    float2 acc = gather8r(g_ell + r * ELLW, (const float2*)g_Xs,
                          beg, end, lane);
    if (half) part[rl][lane] = acc;
    __syncthreads();
    if (!half) {
        float2 p = part[rl][lane];
        acc.x += p.x; acc.y += p.y;

        float dr = g_deg[r];
        float sr = g_sinv[r];
        float diag = 1.0f - 1.0f / dr;
        float2 xr = __ldg(&((const float2*)x)[r * 32 + lane]);
        float2 t1;
        t1.x = fmaf(diag, xr.x, -sr * acc.x);
        t1.y = fmaf(diag, xr.y, -sr * acc.y);
        ((float2*)g_T1)[r * 32 + lane] = t1;
        ((float2*)g_T1s)[r * 32 + lane] = make_float2(sr * t1.x, sr * t1.y);
    }
}

// 4) T2 = 2*(diag*T1[r] - sr * sum w*T1s[c]) - x[r]
__global__ void k_spmm2(const float* __restrict__ x) {
    __shared__ float2 part[4][32];
    int gtid = blockIdx.x * blockDim.x + threadIdx.x;
    int r    = gtid >> 6;
    int half = (threadIdx.x >> 5) & 1;
    int lane = threadIdx.x & 31;
    int rl   = threadIdx.x >> 6;

    int nnz = g_cnt2[r];
    int n0  = (nnz + 1) >> 1;
    int beg = half ? n0 : 0;
    int end = half ? nnz : n0;

    float2 acc = gather8r(g_ell + r * ELLW, (const float2*)g_T1s,
                          beg, end, lane);
    if (half) part[rl][lane] = acc;
    __syncthreads();
    if (!half) {
        float2 p = part[rl][lane];
        acc.x += p.x; acc.y += p.y;

        float dr = g_deg[r];
        float sr = g_sinv[r];
        float diag = 1.0f - 1.0f / dr;
        float2 t1r = __ldg(&((const float2*)g_T1)[r * 32 + lane]);
        float2 x0  = __ldg(&((const float2*)x)[r * 32 + lane]);
        float2 t2;
        t2.x = 2.0f * fmaf(diag, t1r.x, -sr * acc.x) - x0.x;
        t2.y = 2.0f * fmaf(diag, t1r.y, -sr * acc.y) - x0.y;
        ((float2*)g_T2)[r * 32 + lane] = t2;
    }
}

// 5) fused output GEMM: out = x@W0 + T1@W1 + T2@W2 + bias
__global__ void k_out(const float* __restrict__ x,
                      const float* __restrict__ w,
                      const float* __restrict__ bias,
                      float* __restrict__ out) {
    __shared__ float ws[64 * 64];   // current W_m (16 KB)
    __shared__ float ts[32 * 64];   // 32-row tile of T_m (8 KB)
    int tid = threadIdx.x;
    int o  = tid & 63;
    int ty = tid >> 6;              // 0..3
    int r0 = blockIdx.x * 32;

    float b = __ldg(&bias[o]);
    float acc[8];
    #pragma unroll
    for (int q = 0; q < 8; q++) acc[q] = b;

    const float* mats[3];
    mats[0] = x    + r0 * 64;
    mats[1] = g_T1 + r0 * 64;
    mats[2] = g_T2 + r0 * 64;

    for (int m = 0; m < 3; m++) {
        for (int idx = tid; idx < 4096; idx += 256) ws[idx] = w[m * 4096 + idx];
        const float4* src = (const float4*)mats[m];
        float4* dst = (float4*)ts;
        for (int idx = tid; idx < 32 * 16; idx += 256) dst[idx] = src[idx];
        __syncthreads();

        #pragma unroll 2
        for (int i4 = 0; i4 < 16; i4++) {
            float w0 = ws[(i4 * 4 + 0) * 64 + o];
            float w1 = ws[(i4 * 4 + 1) * 64 + o];
            float w2 = ws[(i4 * 4 + 2) * 64 + o];
            float w3 = ws[(i4 * 4 + 3) * 64 + o];
            #pragma unroll
            for (int q = 0; q < 8; q++) {
                float4 tv = ((const float4*)(ts + (ty * 8 + q) * 64))[i4];
                acc[q] = fmaf(tv.x, w0, fmaf(tv.y, w1,
                         fmaf(tv.z, w2, fmaf(tv.w, w3, acc[q]))));
            }
        }
        __syncthreads();
    }
    #pragma unroll
    for (int q = 0; q < 8; q++)
        out[(r0 + ty * 8 + q) * 64 + o] = acc[q];
}

extern "C" void kernel_launch(void* const* d_in, const int* in_sizes, int n_in,
                              void* d_out, int out_size) {
    const float* x    = (const float*)d_in[0];
    const void*  ei   = (const void*)d_in[1];
    const float* ew   = (const float*)d_in[2];
    const float* w    = (const float*)d_in[3];
    const float* aw   = (const float*)d_in[4];
    const float* bias = (const float*)d_in[5];
    float* out = (float*)d_out;

    k_setup  <<<1, 32>>>(ei, aw);
    k_scatter<<<EE / 256, 256>>>(ei);
    k_dedup  <<<NN / 8, 256>>>(ew, x);
    k_spmm1  <<<NN * 64 / 256, 256>>>(x);
    k_spmm2  <<<NN * 64 / 256, 256>>>(x);
    k_out    <<<NN / 32, 256>>>(x, w, bias, out);
}

// round 11
// speedup vs baseline: 1.0019x; 1.0019x over previous
#include <cuda_runtime.h>
#include <cuda_fp16.h>
#include <math.h>

#define NN    8192
#define EE    262144
#define CC    64
#define ELLW  128   // Poisson(32) tail beyond 128 ~ 1e-40

// ---- scratch (__device__ globals; zeroed at module load) ----
__device__ int    g_cnt[NN];           // raw scatter counts (self-reset by dedup)
__device__ int    g_cnt2[NN];          // deduped counts
__device__ float  g_deg[NN];
__device__ float  g_sinv[NN];          // rsqrt(deg)
__device__ int2   g_ellcj[NN * ELLW];  // raw: (col, edge id)
__device__ float2 g_ell[NN * ELLW];    // winners: (col*32 as float-bits, gated weight)
__device__ __half2 g_Xs[NN * 32];      // fp16: sinv[r] * x[r]
__device__ float  g_T1[NN * CC];
__device__ __half2 g_T1s[NN * 32];     // fp16: sinv[r] * T1[r]
__device__ float  g_T2[NN * CC];
__device__ float  g_gate;
__device__ int    g_is32;

__device__ __forceinline__ void load_rc(const void* ei, int j, int& r, int& c) {
    if (g_is32) {
        const int* e = (const int*)ei;
        r = e[j]; c = e[EE + j];
    } else {
        const long long* e = (const long long*)ei;
        r = (int)e[j]; c = (int)e[EE + j];
    }
}

// 0) dtype detect + gate (one warp)
__global__ void k_setup(const void* ei, const float* __restrict__ aw) {
    const long long* e64 = (const long long*)ei;
    int lane = threadIdx.x;
    long long v0 = e64[lane];
    long long v1 = e64[32 + lane];
    int bad = (v0 < 0 || v0 >= NN || v1 < 0 || v1 >= NN);
    unsigned any = __any_sync(0xffffffffu, bad);
    if (lane == 0) {
        g_is32 = any ? 1 : 0;
        g_gate = 1.0f / (1.0f + expf(-aw[0]));
    }
}

// 1) scatter edges into per-row lists (order nondeterministic; j recorded)
__global__ void k_scatter(const void* __restrict__ ei) {
    int j = blockIdx.x * blockDim.x + threadIdx.x;
    if (j >= EE) return;
    int r, c; load_rc(ei, j, r, c);
    int pos = atomicAdd(&g_cnt[r], 1);
    if (pos < ELLW) g_ellcj[r * ELLW + pos] = make_int2(c, j);
}

// 2) per-row dedupe via 256-slot per-warp shared hash.
//    entry = (col+1)<<18 | j  -> atomicMax = last-write-wins on edge id.
//    Also writes Xs[r] = half2(sinv[r]*x[r]). Self-resets g_cnt[r].
__global__ void k_dedup(const float* __restrict__ ew,
                        const float* __restrict__ x) {
    __shared__ unsigned tab[8][256];
    int wid  = threadIdx.x >> 5;
    int lane = threadIdx.x & 31;
    #pragma unroll
    for (int i = 0; i < 8; i++) tab[wid][lane + 32 * i] = 0u;
    __syncwarp();

    int r = blockIdx.x * 8 + wid;
    int nnz = min(g_cnt[r], ELLW);

    for (int k = lane; k < nnz; k += 32) {
        int2 cj = g_ellcj[r * ELLW + k];
        unsigned c = (unsigned)cj.x;
        unsigned entry = ((c + 1u) << 18) | (unsigned)cj.y;
        unsigned h = (c * 2654435761u) >> 24;
        for (;;) {
            unsigned cur = tab[wid][h];
            if (cur == 0u) {
                unsigned old = atomicCAS(&tab[wid][h], 0u, entry);
                if (old == 0u) break;
                cur = old;
            }
            if ((cur >> 18) == c + 1u) { atomicMax(&tab[wid][h], entry); break; }
            h = (h + 1u) & 255u;
        }
    }
    __syncwarp();

    float gate = g_gate;
    float degsum = 0.0f;
    int outpos = 0;
    #pragma unroll
    for (int it = 0; it < 8; it++) {
        unsigned e = tab[wid][lane + 32 * it];
        bool alive = (e != 0u);
        int c = 0; float wv = 0.0f;
        if (alive) {
            c = (int)(e >> 18) - 1;
            int j = (int)(e & 0x3FFFFu);
            wv = __ldg(&ew[j]) * gate;
            degsum += wv;
        }
        unsigned bal = __ballot_sync(0xffffffffu, alive);
        int pos = outpos + __popc(bal & ((1u << lane) - 1u));
        if (alive)
            g_ell[r * ELLW + pos] = make_float2(__int_as_float(c * 32), wv);
        outpos += __popc(bal);
    }
    #pragma unroll
    for (int off = 16; off > 0; off >>= 1)
        degsum += __shfl_xor_sync(0xffffffffu, degsum, off);
    degsum = __shfl_sync(0xffffffffu, degsum, 0);

    float d  = 1.0f + degsum;
    float si = rsqrtf(d);
    if (lane == 0) {
        g_cnt2[r] = outpos;
        g_deg[r]  = d;
        g_sinv[r] = si;
        g_cnt[r]  = 0;              // reset for next replay
    }
    // Xs[r] = half2(sinv[r] * x[r])
    float2 xv = __ldg(&((const float2*)x)[r * 32 + lane]);
    g_Xs[r * 32 + lane] = __floats2half2_rn(xv.x * si, xv.y * si);
}

// chunked fp16 gather core: acc += sum_k w_k * z[c_k], 8-deep forced MLP
__device__ __forceinline__ float2 gather8h(const float2* __restrict__ ell,
                                           const __half2* __restrict__ z,
                                           int nnz, int lane) {
    float2 acc = make_float2(0.0f, 0.0f);
    for (int kb = 0; kb < nnz; kb += 8) {
        float2 e[8];
        #pragma unroll
        for (int u = 0; u < 8; u++) {
            e[u] = (kb + u < nnz) ? __ldg(&ell[kb + u])
                                  : make_float2(__int_as_float(0), 0.0f);
        }
        __half2 zh[8];
        #pragma unroll
        for (int u = 0; u < 8; u++) {
            int cbase = __float_as_int(e[u].x);   // c*32
            zh[u] = __ldg(&z[cbase + lane]);
        }
        #pragma unroll
        for (int u = 0; u < 8; u++) {
            float2 zc = __half22float2(zh[u]);
            acc.x = fmaf(e[u].y, zc.x, acc.x);
            acc.y = fmaf(e[u].y, zc.y, acc.y);
        }
    }
    return acc;
}

// 3) T1 = diag*x[r] - sr * sum w*Xs[c] ; T1 fp32, T1s = half2(sr*T1)
__global__ void k_spmm1(const float* __restrict__ x) {
    int gtid = blockIdx.x * blockDim.x + threadIdx.x;
    int r = gtid >> 5;
    int lane = gtid & 31;

    float dr = g_deg[r];
    float sr = g_sinv[r];
    float diag = 1.0f - 1.0f / dr;

    float2 acc = gather8h(g_ell + r * ELLW, g_Xs, g_cnt2[r], lane);

    float2 xr = __ldg(&((const float2*)x)[r * 32 + lane]);
    float2 t1;
    t1.x = fmaf(diag, xr.x, -sr * acc.x);
    t1.y = fmaf(diag, xr.y, -sr * acc.y);
    ((float2*)g_T1)[r * 32 + lane] = t1;
    g_T1s[r * 32 + lane] = __floats2half2_rn(sr * t1.x, sr * t1.y);
}

// 4) T2 = 2*(diag*T1[r] - sr * sum w*T1s[c]) - x[r]
__global__ void k_spmm2(const float* __restrict__ x) {
    int gtid = blockIdx.x * blockDim.x + threadIdx.x;
    int r = gtid >> 5;
    int lane = gtid & 31;

    float dr = g_deg[r];
    float sr = g_sinv[r];
    float diag = 1.0f - 1.0f / dr;

    float2 acc = gather8h(g_ell + r * ELLW, g_T1s, g_cnt2[r], lane);

    float2 t1r = __ldg(&((const float2*)g_T1)[r * 32 + lane]);
    float2 x0  = __ldg(&((const float2*)x)[r * 32 + lane]);
    float2 t2;
    t2.x = 2.0f * fmaf(diag, t1r.x, -sr * acc.x) - x0.x;
    t2.y = 2.0f * fmaf(diag, t1r.y, -sr * acc.y) - x0.y;
    ((float2*)g_T2)[r * 32 + lane] = t2;
}

// 5) fused output GEMM: out = x@W0 + T1@W1 + T2@W2 + bias
__global__ void k_out(const float* __restrict__ x,
                      const float* __restrict__ w,
                      const float* __restrict__ bias,
                      float* __restrict__ out) {
    __shared__ float ws[64 * 64];   // current W_m (16 KB)
    __shared__ float ts[32 * 64];   // 32-row tile of T_m (8 KB)
    int tid = threadIdx.x;
    int o  = tid & 63;
    int ty = tid >> 6;              // 0..3
    int r0 = blockIdx.x * 32;

    float b = __ldg(&bias[o]);
    float acc[8];
    #pragma unroll
    for (int q = 0; q < 8; q++) acc[q] = b;

    const float* mats[3];
    mats[0] = x    + r0 * 64;
    mats[1] = g_T1 + r0 * 64;
    mats[2] = g_T2 + r0 * 64;

    for (int m = 0; m < 3; m++) {
        for (int idx = tid; idx < 4096; idx += 256) ws[idx] = w[m * 4096 + idx];
        const float4* src = (const float4*)mats[m];
        float4* dst = (float4*)ts;
        for (int idx = tid; idx < 32 * 16; idx += 256) dst[idx] = src[idx];
        __syncthreads();

        #pragma unroll 2
        for (int i4 = 0; i4 < 16; i4++) {
            float w0 = ws[(i4 * 4 + 0) * 64 + o];
            float w1 = ws[(i4 * 4 + 1) * 64 + o];
            float w2 = ws[(i4 * 4 + 2) * 64 + o];
            float w3 = ws[(i4 * 4 + 3) * 64 + o];
            #pragma unroll
            for (int q = 0; q < 8; q++) {
                float4 tv = ((const float4*)(ts + (ty * 8 + q) * 64))[i4];
                acc[q] = fmaf(tv.x, w0, fmaf(tv.y, w1,
                         fmaf(tv.z, w2, fmaf(tv.w, w3, acc[q]))));
            }
        }
        __syncthreads();
    }
    #pragma unroll
    for (int q = 0; q < 8; q++)
        out[(r0 + ty * 8 + q) * 64 + o] = acc[q];
}

extern "C" void kernel_launch(void* const* d_in, const int* in_sizes, int n_in,
                              void* d_out, int out_size) {
    const float* x    = (const float*)d_in[0];
    const void*  ei   = (const void*)d_in[1];
    const float* ew   = (const float*)d_in[2];
    const float* w    = (const float*)d_in[3];
    const float* aw   = (const float*)d_in[4];
    const float* bias = (const float*)d_in[5];
    float* out = (float*)d_out;

    k_setup  <<<1, 32>>>(ei, aw);
    k_scatter<<<EE / 256, 256>>>(ei);
    k_dedup  <<<NN / 8, 256>>>(ew, x);
    k_spmm1  <<<NN * 32 / 256, 256>>>(x);
    k_spmm2  <<<NN * 32 / 256, 256>>>(x);
    k_out    <<<NN / 32, 256>>>(x, w, bias, out);
}

// round 13
// speedup vs baseline: 1.1640x; 1.1619x over previous
#include <cuda_runtime.h>
#include <cuda_fp16.h>
#include <math.h>

#define NN    8192
#define EE    262144
#define CC    64
#define ELLW  128   // Poisson(32) tail beyond 128 ~ 1e-40

// ---- scratch (__device__ globals; zeroed at module load) ----
__device__ int    g_cnt[NN];           // raw scatter counts (self-reset by dedup)
__device__ int    g_cnt2[NN];          // deduped counts, padded to multiple of 8
__device__ float  g_deg[NN];
__device__ float  g_sinv[NN];          // rsqrt(deg)
__device__ int2   g_ellcj[NN * ELLW];  // raw: (col, edge id)
__device__ float2 g_ell[NN * ELLW];    // winners: (col*32 as int-bits, gated weight); zero-padded
__device__ __half2 g_Xs[NN * 32];      // fp16: sinv[r] * x[r]
__device__ float  g_T1[NN * CC];
__device__ __half2 g_T1s[NN * 32];     // fp16: sinv[r] * T1[r]
__device__ float  g_T2[NN * CC];
__device__ float  g_gate;
__device__ int    g_is32;

__device__ __forceinline__ void load_rc(const void* ei, int j, int& r, int& c) {
    if (g_is32) {
        const int* e = (const int*)ei;
        r = e[j]; c = e[EE + j];
    } else {
        const long long* e = (const long long*)ei;
        r = (int)e[j]; c = (int)e[EE + j];
    }
}

// 0) dtype detect + gate (one warp)
__global__ void k_setup(const void* ei, const float* __restrict__ aw) {
    const long long* e64 = (const long long*)ei;
    int lane = threadIdx.x;
    long long v0 = e64[lane];
    long long v1 = e64[32 + lane];
    int bad = (v0 < 0 || v0 >= NN || v1 < 0 || v1 >= NN);
    unsigned any = __any_sync(0xffffffffu, bad);
    if (lane == 0) {
        g_is32 = any ? 1 : 0;
        g_gate = 1.0f / (1.0f + expf(-aw[0]));
    }
}

// 1) scatter edges into per-row lists (order nondeterministic; j recorded)
__global__ void k_scatter(const void* __restrict__ ei) {
    int j = blockIdx.x * blockDim.x + threadIdx.x;
    if (j >= EE) return;
    int r, c; load_rc(ei, j, r, c);
    int pos = atomicAdd(&g_cnt[r], 1);
    if (pos < ELLW) g_ellcj[r * ELLW + pos] = make_int2(c, j);
}

// 2) per-row dedupe via 256-slot per-warp shared hash.
//    entry = (col+1)<<18 | j  -> atomicMax = last-write-wins on edge id.
//    Pads output list to multiple of 8 with zero-weight entries.
//    Also writes Xs[r] = half2(sinv[r]*x[r]). Self-resets g_cnt[r].
__global__ void k_dedup(const float* __restrict__ ew,
                        const float* __restrict__ x) {
    __shared__ unsigned tab[8][256];
    int wid  = threadIdx.x >> 5;
    int lane = threadIdx.x & 31;
    #pragma unroll
    for (int i = 0; i < 8; i++) tab[wid][lane + 32 * i] = 0u;
    __syncwarp();

    int r = blockIdx.x * 8 + wid;
    int nnz = min(g_cnt[r], ELLW);

    for (int k = lane; k < nnz; k += 32) {
        int2 cj = g_ellcj[r * ELLW + k];
        unsigned c = (unsigned)cj.x;
        unsigned entry = ((c + 1u) << 18) | (unsigned)cj.y;
        unsigned h = (c * 2654435761u) >> 24;
        for (;;) {
            unsigned cur = tab[wid][h];
            if (cur == 0u) {
                unsigned old = atomicCAS(&tab[wid][h], 0u, entry);
                if (old == 0u) break;
                cur = old;
            }
            if ((cur >> 18) == c + 1u) { atomicMax(&tab[wid][h], entry); break; }
            h = (h + 1u) & 255u;
        }
    }
    __syncwarp();

    float gate = g_gate;
    float degsum = 0.0f;
    int outpos = 0;
    #pragma unroll
    for (int it = 0; it < 8; it++) {
        unsigned e = tab[wid][lane + 32 * it];
        bool alive = (e != 0u);
        int c = 0; float wv = 0.0f;
        if (alive) {
            c = (int)(e >> 18) - 1;
            int j = (int)(e & 0x3FFFFu);
            wv = __ldg(&ew[j]) * gate;
            degsum += wv;
        }
        unsigned bal = __ballot_sync(0xffffffffu, alive);
        int pos = outpos + __popc(bal & ((1u << lane) - 1u));
        if (alive)
            g_ell[r * ELLW + pos] = make_float2(__int_as_float(c * 32), wv);
        outpos += __popc(bal);
    }
    // pad to multiple of 8 with zero-weight entries (point at row 0)
    int pad = (8 - (outpos & 7)) & 7;
    if (lane < pad)
        g_ell[r * ELLW + outpos + lane] = make_float2(__int_as_float(0), 0.0f);

    #pragma unroll
    for (int off = 16; off > 0; off >>= 1)
        degsum += __shfl_xor_sync(0xffffffffu, degsum, off);
    degsum = __shfl_sync(0xffffffffu, degsum, 0);

    float d  = 1.0f + degsum;
    float si = rsqrtf(d);
    if (lane == 0) {
        g_cnt2[r] = outpos + pad;   // padded count
        g_deg[r]  = d;
        g_sinv[r] = si;
        g_cnt[r]  = 0;              // reset for next replay
    }
    // Xs[r] = half2(sinv[r] * x[r])
    float2 xv = __ldg(&((const float2*)x)[r * 32 + lane]);
    g_Xs[r * 32 + lane] = __floats2half2_rn(xv.x * si, xv.y * si);
}

// chunked fp16 gather core over padded list: no predication, float4 ell loads
__device__ __forceinline__ float2 gather8h(const float2* __restrict__ ell,
                                           const __half2* __restrict__ z,
                                           int nnzp, int lane) {
    float2 acc = make_float2(0.0f, 0.0f);
    const __half2* __restrict__ zp = z + lane;
    const float4* __restrict__ e4 = (const float4*)ell;
    for (int kb = 0; kb < nnzp; kb += 8) {
        float4 e0 = __ldg(e4 + 0);
        float4 e1 = __ldg(e4 + 1);
        float4 e2 = __ldg(e4 + 2);
        float4 e3 = __ldg(e4 + 3);
        e4 += 4;
        __half2 z0 = __ldg(zp + __float_as_int(e0.x));
        __half2 z1 = __ldg(zp + __float_as_int(e0.z));
        __half2 z2 = __ldg(zp + __float_as_int(e1.x));
        __half2 z3 = __ldg(zp + __float_as_int(e1.z));
        __half2 z4 = __ldg(zp + __float_as_int(e2.x));
        __half2 z5 = __ldg(zp + __float_as_int(e2.z));
        __half2 z6 = __ldg(zp + __float_as_int(e3.x));
        __half2 z7 = __ldg(zp + __float_as_int(e3.z));
        float2 f;
        f = __half22float2(z0); acc.x = fmaf(e0.y, f.x, acc.x); acc.y = fmaf(e0.y, f.y, acc.y);
        f = __half22float2(z1); acc.x = fmaf(e0.w, f.x, acc.x); acc.y = fmaf(e0.w, f.y, acc.y);
        f = __half22float2(z2); acc.x = fmaf(e1.y, f.x, acc.x); acc.y = fmaf(e1.y, f.y, acc.y);
        f = __half22float2(z3); acc.x = fmaf(e1.w, f.x, acc.x); acc.y = fmaf(e1.w, f.y, acc.y);
        f = __half22float2(z4); acc.x = fmaf(e2.y, f.x, acc.x); acc.y = fmaf(e2.y, f.y, acc.y);
        f = __half22float2(z5); acc.x = fmaf(e2.w, f.x, acc.x); acc.y = fmaf(e2.w, f.y, acc.y);
        f = __half22float2(z6); acc.x = fmaf(e3.y, f.x, acc.x); acc.y = fmaf(e3.y, f.y, acc.y);
        f = __half22float2(z7); acc.x = fmaf(e3.w, f.x, acc.x); acc.y = fmaf(e3.w, f.y, acc.y);
    }
    return acc;
}

// 3) T1 = diag*x[r] - sr * sum w*Xs[c] ; T1 fp32, T1s = half2(sr*T1)
__global__ void k_spmm1(const float* __restrict__ x) {
    int gtid = blockIdx.x * blockDim.x + threadIdx.x;
    int r = gtid >> 5;
    int lane = gtid & 31;

    float dr = g_deg[r];
    float sr = g_sinv[r];
    float diag = 1.0f - 1.0f / dr;

    float2 acc = gather8h(g_ell + r * ELLW, g_Xs, g_cnt2[r], lane);

    float2 xr = __ldg(&((const float2*)x)[r * 32 + lane]);
    float2 t1;
    t1.x = fmaf(diag, xr.x, -sr * acc.x);
    t1.y = fmaf(diag, xr.y, -sr * acc.y);
    ((float2*)g_T1)[r * 32 + lane] = t1;
    g_T1s[r * 32 + lane] = __floats2half2_rn(sr * t1.x, sr * t1.y);
}

// 4) T2 = 2*(diag*T1[r] - sr * sum w*T1s[c]) - x[r]
__global__ void k_spmm2(const float* __restrict__ x) {
    int gtid = blockIdx.x * blockDim.x + threadIdx.x;
    int r = gtid >> 5;
    int lane = gtid & 31;

    float dr = g_deg[r];
    float sr = g_sinv[r];
    float diag = 1.0f - 1.0f / dr;

    float2 acc = gather8h(g_ell + r * ELLW, g_T1s, g_cnt2[r], lane);

    float2 t1r = __ldg(&((const float2*)g_T1)[r * 32 + lane]);
    float2 x0  = __ldg(&((const float2*)x)[r * 32 + lane]);
    float2 t2;
    t2.x = 2.0f * fmaf(diag, t1r.x, -sr * acc.x) - x0.x;
    t2.y = 2.0f * fmaf(diag, t1r.y, -sr * acc.y) - x0.y;
    ((float2*)g_T2)[r * 32 + lane] = t2;
}

// 5) fused output GEMM: out = x@W0 + T1@W1 + T2@W2 + bias
__global__ void k_out(const float* __restrict__ x,
                      const float* __restrict__ w,
                      const float* __restrict__ bias,
                      float* __restrict__ out) {
    __shared__ float ws[64 * 64];   // current W_m (16 KB)
    __shared__ float ts[32 * 64];   // 32-row tile of T_m (8 KB)
    int tid = threadIdx.x;
    int o  = tid & 63;
    int ty = tid >> 6;              // 0..3
    int r0 = blockIdx.x * 32;

    float b = __ldg(&bias[o]);
    float acc[8];
    #pragma unroll
    for (int q = 0; q < 8; q++) acc[q] = b;

    const float* mats[3];
    mats[0] = x    + r0 * 64;
    mats[1] = g_T1 + r0 * 64;
    mats[2] = g_T2 + r0 * 64;

    for (int m = 0; m < 3; m++) {
        for (int idx = tid; idx < 4096; idx += 256) ws[idx] = w[m * 4096 + idx];
        const float4* src = (const float4*)mats[m];
        float4* dst = (float4*)ts;
        for (int idx = tid; idx < 32 * 16; idx += 256) dst[idx] = src[idx];
        __syncthreads();

        #pragma unroll 2
        for (int i4 = 0; i4 < 16; i4++) {
            float w0 = ws[(i4 * 4 + 0) * 64 + o];
            float w1 = ws[(i4 * 4 + 1) * 64 + o];
            float w2 = ws[(i4 * 4 + 2) * 64 + o];
            float w3 = ws[(i4 * 4 + 3) * 64 + o];
            #pragma unroll
            for (int q = 0; q < 8; q++) {
                float4 tv = ((const float4*)(ts + (ty * 8 + q) * 64))[i4];
                acc[q] = fmaf(tv.x, w0, fmaf(tv.y, w1,
                         fmaf(tv.z, w2, fmaf(tv.w, w3, acc[q]))));
            }
        }
        __syncthreads();
    }
    #pragma unroll
    for (int q = 0; q < 8; q++)
        out[(r0 + ty * 8 + q) * 64 + o] = acc[q];
}

extern "C" void kernel_launch(void* const* d_in, const int* in_sizes, int n_in,
                              void* d_out, int out_size) {
    const float* x    = (const float*)d_in[0];
    const void*  ei   = (const void*)d_in[1];
    const float* ew   = (const float*)d_in[2];
    const float* w    = (const float*)d_in[3];
    const float* aw   = (const float*)d_in[4];
    const float* bias = (const float*)d_in[5];
    float* out = (float*)d_out;

    k_setup  <<<1, 32>>>(ei, aw);
    k_scatter<<<EE / 256, 256>>>(ei);
    k_dedup  <<<NN / 8, 256>>>(ew, x);
    k_spmm1  <<<NN * 32 / 256, 256>>>(x);
    k_spmm2  <<<NN * 32 / 256, 256>>>(x);
    k_out    <<<NN / 32, 256>>>(x, w, bias, out);
}